// round 5
// baseline (speedup 1.0000x reference)
#include <cuda_runtime.h>
#include <math.h>

#define FDIM 256
#define BMAX 1024
#define MMAX 500000
#define NMAX 200000

// Scratch (allocation-free: __device__ globals)
__device__ float    g_groot[BMAX * FDIM];   // per-root x_r * w_ego_root * w_ego_u
__device__ float2   g_rootsc[BMAX];         // {1/max(nr,eps), budgets/200}
__device__ float    g_sv[BMAX];             // x_r . w_layer_v
__device__ unsigned g_pnorm[BMAX];          // encoded float max
__device__ float    g_agg[MMAX];            // segment_sum(sv[edge_src] -> edge_dst)
__device__ float    g_pu[MMAX];             // p_u before normalization
__device__ float4   g_node[NMAX];           // {1/max(nu,eps), su, 0.5*n_imp, 0}

__device__ __forceinline__ unsigned f2key(float f) {
    unsigned u = __float_as_uint(f);
    return (u & 0x80000000u) ? ~u : (u | 0x80000000u);
}
__device__ __forceinline__ float key2f(unsigned k) {
    unsigned u = (k & 0x80000000u) ? (k ^ 0x80000000u) : ~k;
    return __uint_as_float(u);
}
__device__ __forceinline__ float dot4(float4 a, float4 b) {
    return a.x * b.x + a.y * b.y + a.z * b.z + a.w * b.w;
}
__device__ __forceinline__ float sq8(float4 a, float4 b, float4 wa, float4 wb) {
    float x0 = a.x*wa.x, x1 = a.y*wa.y, x2 = a.z*wa.z, x3 = a.w*wa.w;
    float y0 = b.x*wb.x, y1 = b.y*wb.y, y2 = b.z*wb.z, y3 = b.w*wb.w;
    return x0*x0 + x1*x1 + x2*x2 + x3*x3 + y0*y0 + y1*y1 + y2*y2 + y3*y3;
}

// K1: per-root precompute (one block per root) + zero g_agg (strided).
__global__ void k_root(const float* __restrict__ x,
                       const float* __restrict__ w_ego_root,
                       const float* __restrict__ w_ego_u,
                       const float* __restrict__ w_layer_v,
                       const float* __restrict__ budgets,
                       const int*   __restrict__ batch_nodes,
                       int B, int M)
{
    int b = blockIdx.x;
    int f = threadIdx.x;

    for (int j = b * FDIM + f; j < M; j += gridDim.x * FDIM) g_agg[j] = 0.0f;

    float xr = x[(size_t)batch_nodes[b] * FDIM + f];
    float h  = xr * w_ego_root[f];
    g_groot[b * FDIM + f] = h * w_ego_u[f];
    float s1 = h * h;
    float s2 = xr * w_layer_v[f];

    __shared__ float sh1[8], sh2[8];
    #pragma unroll
    for (int o = 16; o; o >>= 1) {
        s1 += __shfl_xor_sync(0xffffffffu, s1, o);
        s2 += __shfl_xor_sync(0xffffffffu, s2, o);
    }
    int w = f >> 5, l = f & 31;
    if (l == 0) { sh1[w] = s1; sh2[w] = s2; }
    __syncthreads();
    if (f == 0) {
        float t1 = 0.f, t2 = 0.f;
        #pragma unroll
        for (int i = 0; i < 8; i++) { t1 += sh1[i]; t2 += sh2[i]; }
        g_rootsc[b] = make_float2(1.0f / fmaxf(sqrtf(t1), 1e-6f),
                                  budgets[b] * (1.0f / 200.0f));
        g_sv[b] = t2;
        g_pnorm[b] = f2key(-INFINITY);
    }
}

// K2: per-node precompute: nu, su, n_imp packed as float4. Streams x once.
__global__ void __launch_bounds__(256)
k_pre(const float* __restrict__ x,
      const float* __restrict__ w_ego_u,
      const float* __restrict__ w_layer_u,
      const float* __restrict__ n_imp, int N)
{
    int lane = threadIdx.x & 31;
    int gw = (blockIdx.x * blockDim.x + threadIdx.x) >> 5;
    int nw = gridDim.x * (blockDim.x >> 5);
    const float4* x4 = (const float4*)x;

    float4 wea = __ldg(((const float4*)w_ego_u)   + lane);
    float4 web = __ldg(((const float4*)w_ego_u)   + lane + 32);
    float4 wla = __ldg(((const float4*)w_layer_u) + lane);
    float4 wlb = __ldg(((const float4*)w_layer_u) + lane + 32);

    for (int n = gw * 2; n < N; n += nw * 2) {
        bool two = (n + 1 < N);
        float4 a0 = __ldg(x4 + (size_t)n * 64 + lane);
        float4 b0 = __ldg(x4 + (size_t)n * 64 + lane + 32);
        int n1 = two ? n + 1 : n;
        float4 a1 = __ldg(x4 + (size_t)n1 * 64 + lane);
        float4 b1 = __ldg(x4 + (size_t)n1 * 64 + lane + 32);

        float nu0 = sq8(a0, b0, wea, web);
        float su0 = dot4(a0, wla) + dot4(b0, wlb);
        float nu1 = sq8(a1, b1, wea, web);
        float su1 = dot4(a1, wla) + dot4(b1, wlb);

        nu0 += __shfl_xor_sync(0xffffffffu, nu0, 16);
        su0 += __shfl_xor_sync(0xffffffffu, su0, 16);
        nu1 += __shfl_xor_sync(0xffffffffu, nu1, 16);
        su1 += __shfl_xor_sync(0xffffffffu, su1, 16);
        bool hi16 = (lane & 16) != 0;
        float v0 = hi16 ? su0 : nu0;      // lanes<16: nu, >=16: su
        float v1 = hi16 ? su1 : nu1;
        #pragma unroll
        for (int o = 8; o; o >>= 1) {
            v0 += __shfl_xor_sync(0xffffffffu, v0, o);
            v1 += __shfl_xor_sync(0xffffffffu, v1, o);
        }
        float su0f = __shfl_sync(0xffffffffu, v0, 16);
        float su1f = __shfl_sync(0xffffffffu, v1, 16);
        if (lane == 0) {
            g_node[n] = make_float4(1.0f / fmaxf(sqrtf(v0), 1e-6f), su0f,
                                    0.5f * __ldg(n_imp + n), 0.0f);
            if (two)
                g_node[n1] = make_float4(1.0f / fmaxf(sqrtf(v1), 1e-6f), su1f,
                                         0.5f * __ldg(n_imp + n1), 0.0f);
        }
    }
}

// K3: edge scatter-add (4 edges per thread)
__global__ void k_edge(const int* __restrict__ edge_src,
                       const int* __restrict__ edge_dst, int E)
{
    int i = (blockIdx.x * blockDim.x + threadIdx.x) * 4;
    if (i + 3 < E) {
        int4 s = *(const int4*)(edge_src + i);
        int4 d = *(const int4*)(edge_dst + i);
        atomicAdd(&g_agg[d.x], g_sv[s.x]);
        atomicAdd(&g_agg[d.y], g_sv[s.y]);
        atomicAdd(&g_agg[d.z], g_sv[s.z]);
        atomicAdd(&g_agg[d.w], g_sv[s.w]);
    } else {
        for (int j = i; j < E; j++)
            atomicAdd(&g_agg[edge_dst[j]], g_sv[edge_src[j]]);
    }
}

// K4: dot-only candidate kernel. Warp handles 16 contiguous candidates in
// 4-cand iterations; g_groot row cached in registers across iterations
// (batch_ptr sorted, run length ~488, so the cache almost always hits).
__global__ void __launch_bounds__(256)
k_cand(const float* __restrict__ x,
       const int* __restrict__ u_ids,
       const int* __restrict__ batch_ptr, int M)
{
    int lane = threadIdx.x & 31;
    int gwarp = (blockIdx.x * blockDim.x + threadIdx.x) >> 5;
    int base = gwarp * 16;
    if (base >= M) return;
    int lim = base + 16; if (lim > M) lim = M;

    const float4* x4 = (const float4*)x;
    const float4* g4 = (const float4*)g_groot;

    int bcache = -1;
    float4 ga = make_float4(0.f,0.f,0.f,0.f), gb = ga;

    for (int m0 = base; m0 < lim; m0 += 4) {
        if (m0 + 3 < lim) {
            int4 uu = *(const int4*)(u_ids + m0);
            int4 bb = *(const int4*)(batch_ptr + m0);

            float4 xa0 = __ldg(x4 + (size_t)uu.x * 64 + lane);
            float4 xb0 = __ldg(x4 + (size_t)uu.x * 64 + lane + 32);
            float4 xa1 = __ldg(x4 + (size_t)uu.y * 64 + lane);
            float4 xb1 = __ldg(x4 + (size_t)uu.y * 64 + lane + 32);
            float4 xa2 = __ldg(x4 + (size_t)uu.z * 64 + lane);
            float4 xb2 = __ldg(x4 + (size_t)uu.z * 64 + lane + 32);
            float4 xa3 = __ldg(x4 + (size_t)uu.w * 64 + lane);
            float4 xb3 = __ldg(x4 + (size_t)uu.w * 64 + lane + 32);

            float d0, d1, d2, d3;
            bool uni = (bb.x == bb.y) && (bb.x == bb.z) && (bb.x == bb.w);
            if (uni) {
                if (bb.x != bcache) {
                    ga = __ldg(g4 + (size_t)bb.x * 64 + lane);
                    gb = __ldg(g4 + (size_t)bb.x * 64 + lane + 32);
                    bcache = bb.x;
                }
                d0 = dot4(xa0, ga) + dot4(xb0, gb);
                d1 = dot4(xa1, ga) + dot4(xb1, gb);
                d2 = dot4(xa2, ga) + dot4(xb2, gb);
                d3 = dot4(xa3, ga) + dot4(xb3, gb);
            } else {
                bcache = -1;
                float4 t0 = __ldg(g4 + (size_t)bb.x * 64 + lane);
                float4 t1 = __ldg(g4 + (size_t)bb.x * 64 + lane + 32);
                d0 = dot4(xa0, t0) + dot4(xb0, t1);
                t0 = __ldg(g4 + (size_t)bb.y * 64 + lane);
                t1 = __ldg(g4 + (size_t)bb.y * 64 + lane + 32);
                d1 = dot4(xa1, t0) + dot4(xb1, t1);
                t0 = __ldg(g4 + (size_t)bb.z * 64 + lane);
                t1 = __ldg(g4 + (size_t)bb.z * 64 + lane + 32);
                d2 = dot4(xa2, t0) + dot4(xb2, t1);
                t0 = __ldg(g4 + (size_t)bb.w * 64 + lane);
                t1 = __ldg(g4 + (size_t)bb.w * 64 + lane + 32);
                d3 = dot4(xa3, t0) + dot4(xb3, t1);
            }

            // folded reduction: 4 dots in 9 shuffles
            d0 += __shfl_xor_sync(0xffffffffu, d0, 16);
            d1 += __shfl_xor_sync(0xffffffffu, d1, 16);
            d2 += __shfl_xor_sync(0xffffffffu, d2, 16);
            d3 += __shfl_xor_sync(0xffffffffu, d3, 16);
            bool hi16 = (lane & 16) != 0;
            float dA = hi16 ? d1 : d0;
            float dB = hi16 ? d3 : d2;
            dA += __shfl_xor_sync(0xffffffffu, dA, 8);
            dB += __shfl_xor_sync(0xffffffffu, dB, 8);
            bool hi8 = (lane & 8) != 0;
            float d = hi8 ? dB : dA;
            #pragma unroll
            for (int o = 4; o; o >>= 1)
                d += __shfl_xor_sync(0xffffffffu, d, o);
            // lanes 0,8,16,24 hold candidates 0,2,1,3

            if ((lane & 7) == 0) {
                int ci = ((lane >> 3) & 1) * 2 + ((lane >> 4) & 1);
                int m = m0 + ci;
                int u = (ci == 0) ? uu.x : (ci == 1) ? uu.y : (ci == 2) ? uu.z : uu.w;
                int b = (ci == 0) ? bb.x : (ci == 1) ? bb.y : (ci == 2) ? bb.z : bb.w;
                float4 nd = __ldg((const float4*)g_node + u);  // {invnu, su, hni}
                float2 rs = __ldg(g_rootsc + b);               // {invnr, bf}
                float ag = g_agg[m];
                float ego = d * rs.x * nd.x;
                float p = (ego + tanhf(ag + nd.y)) * nd.z * rs.y;
                g_pu[m] = p;
                atomicMax(&g_pnorm[b], f2key(p));
            }
        } else {
            for (int m = m0; m < lim; m++) {
                int u = __ldg(u_ids + m);
                int b = __ldg(batch_ptr + m);
                float4 xa = __ldg(x4 + (size_t)u * 64 + lane);
                float4 xb = __ldg(x4 + (size_t)u * 64 + lane + 32);
                float4 t0 = __ldg(g4 + (size_t)b * 64 + lane);
                float4 t1 = __ldg(g4 + (size_t)b * 64 + lane + 32);
                float d = dot4(xa, t0) + dot4(xb, t1);
                #pragma unroll
                for (int o = 16; o; o >>= 1)
                    d += __shfl_xor_sync(0xffffffffu, d, o);
                if (lane == 0) {
                    float4 nd = __ldg((const float4*)g_node + u);
                    float2 rs = __ldg(g_rootsc + b);
                    float ego = d * rs.x * nd.x;
                    float p = (ego + tanhf(g_agg[m] + nd.y)) * nd.z * rs.y;
                    g_pu[m] = p;
                    atomicMax(&g_pnorm[b], f2key(p));
                }
            }
        }
    }
}

// K5: normalize + nan/inf replace + clip (vectorized)
__global__ void k_final(const int* __restrict__ batch_ptr,
                        float* __restrict__ out, int M)
{
    int m = (blockIdx.x * blockDim.x + threadIdx.x) * 4;
    if (m + 3 < M) {
        int4   bp = *(const int4*)(batch_ptr + m);
        float4 pu = *(const float4*)(g_pu + m);
        float4 r;
        {
            float p = pu.x / key2f(g_pnorm[bp.x]) + 1.0f;
            if (isnan(p)) p = 0.0f; else if (isinf(p)) p = 1.0f;
            r.x = fminf(fmaxf(p, 1e-5f), 1.0f);
        }
        {
            float p = pu.y / key2f(g_pnorm[bp.y]) + 1.0f;
            if (isnan(p)) p = 0.0f; else if (isinf(p)) p = 1.0f;
            r.y = fminf(fmaxf(p, 1e-5f), 1.0f);
        }
        {
            float p = pu.z / key2f(g_pnorm[bp.z]) + 1.0f;
            if (isnan(p)) p = 0.0f; else if (isinf(p)) p = 1.0f;
            r.z = fminf(fmaxf(p, 1e-5f), 1.0f);
        }
        {
            float p = pu.w / key2f(g_pnorm[bp.w]) + 1.0f;
            if (isnan(p)) p = 0.0f; else if (isinf(p)) p = 1.0f;
            r.w = fminf(fmaxf(p, 1e-5f), 1.0f);
        }
        *(float4*)(out + m) = r;
    } else {
        for (int j = m; j < M; j++) {
            float p = g_pu[j] / key2f(g_pnorm[batch_ptr[j]]) + 1.0f;
            if (isnan(p)) p = 0.0f; else if (isinf(p)) p = 1.0f;
            out[j] = fminf(fmaxf(p, 1e-5f), 1.0f);
        }
    }
}

extern "C" void kernel_launch(void* const* d_in, const int* in_sizes, int n_in,
                              void* d_out, int out_size)
{
    const float* x           = (const float*)d_in[0];
    const float* w_ego_root  = (const float*)d_in[1];
    const float* w_ego_u     = (const float*)d_in[2];
    const float* w_layer_v   = (const float*)d_in[3];
    const float* w_layer_u   = (const float*)d_in[4];
    const float* n_imp       = (const float*)d_in[5];
    const float* budgets     = (const float*)d_in[6];
    const int*   batch_nodes = (const int*)d_in[7];
    const int*   u_ids       = (const int*)d_in[8];
    const int*   batch_ptr   = (const int*)d_in[9];
    const int*   edge_src    = (const int*)d_in[10];
    const int*   edge_dst    = (const int*)d_in[11];
    float* out = (float*)d_out;

    int B = in_sizes[7];
    int M = in_sizes[8];
    int E = in_sizes[10];
    int N = in_sizes[0] / FDIM;

    k_root<<<B, FDIM>>>(x, w_ego_root, w_ego_u, w_layer_v, budgets,
                        batch_nodes, B, M);
    k_pre<<<2048, 256>>>(x, w_ego_u, w_layer_u, n_imp, N);
    k_edge<<<(E / 4 + 255) / 256, 256>>>(edge_src, edge_dst, E);

    int nwarps = (M + 15) / 16;
    int nblocks = (nwarps + 7) / 8;
    k_cand<<<nblocks, 256>>>(x, u_ids, batch_ptr, M);

    k_final<<<(M / 4 + 255) / 256, 256>>>(batch_ptr, out, M);
}

// round 6
// speedup vs baseline: 1.2127x; 1.2127x over previous
#include <cuda_runtime.h>
#include <math.h>

#define FDIM 256
#define BMAX 1024
#define MMAX 500000
#define NMAX 200000

// Scratch (allocation-free: __device__ globals)
__device__ float    g_groot[BMAX * FDIM];   // per-root x_r * w_ego_root * w_ego_u
__device__ float2   g_rootsc[BMAX];         // {1/max(nr,eps), budgets/200}
__device__ float    g_sv[BMAX];             // x_r . w_layer_v
__device__ unsigned g_pnorm[BMAX];          // encoded float max
__device__ float    g_agg[MMAX];            // segment_sum(sv[edge_src] -> edge_dst)
__device__ float    g_pu[MMAX];             // p_u before normalization
__device__ float4   g_node[NMAX];           // {1/max(nu,eps), su, 0.5*n_imp, 0}

__device__ __forceinline__ unsigned f2key(float f) {
    unsigned u = __float_as_uint(f);
    return (u & 0x80000000u) ? ~u : (u | 0x80000000u);
}
__device__ __forceinline__ float key2f(unsigned k) {
    unsigned u = (k & 0x80000000u) ? (k ^ 0x80000000u) : ~k;
    return __uint_as_float(u);
}
__device__ __forceinline__ float dot4(float4 a, float4 b) {
    return a.x * b.x + a.y * b.y + a.z * b.z + a.w * b.w;
}
__device__ __forceinline__ float sq8(float4 a, float4 b, float4 wa, float4 wb) {
    float x0 = a.x*wa.x, x1 = a.y*wa.y, x2 = a.z*wa.z, x3 = a.w*wa.w;
    float y0 = b.x*wb.x, y1 = b.y*wb.y, y2 = b.z*wb.z, y3 = b.w*wb.w;
    return x0*x0 + x1*x1 + x2*x2 + x3*x3 + y0*y0 + y1*y1 + y2*y2 + y3*y3;
}

// K1: per-root precompute (one block per root) + zero g_agg (strided).
__global__ void k_root(const float* __restrict__ x,
                       const float* __restrict__ w_ego_root,
                       const float* __restrict__ w_ego_u,
                       const float* __restrict__ w_layer_v,
                       const float* __restrict__ budgets,
                       const int*   __restrict__ batch_nodes,
                       int B, int M)
{
    int b = blockIdx.x;
    int f = threadIdx.x;

    for (int j = b * FDIM + f; j < M; j += gridDim.x * FDIM) g_agg[j] = 0.0f;

    float xr = x[(size_t)batch_nodes[b] * FDIM + f];
    float h  = xr * w_ego_root[f];
    g_groot[b * FDIM + f] = h * w_ego_u[f];
    float s1 = h * h;
    float s2 = xr * w_layer_v[f];

    __shared__ float sh1[8], sh2[8];
    #pragma unroll
    for (int o = 16; o; o >>= 1) {
        s1 += __shfl_xor_sync(0xffffffffu, s1, o);
        s2 += __shfl_xor_sync(0xffffffffu, s2, o);
    }
    int w = f >> 5, l = f & 31;
    if (l == 0) { sh1[w] = s1; sh2[w] = s2; }
    __syncthreads();
    if (f == 0) {
        float t1 = 0.f, t2 = 0.f;
        #pragma unroll
        for (int i = 0; i < 8; i++) { t1 += sh1[i]; t2 += sh2[i]; }
        g_rootsc[b] = make_float2(1.0f / fmaxf(sqrtf(t1), 1e-6f),
                                  budgets[b] * (1.0f / 200.0f));
        g_sv[b] = t2;
        g_pnorm[b] = f2key(-INFINITY);
    }
}

// K2: per-node precompute: nu, su, n_imp packed as float4. Streams x once.
__global__ void __launch_bounds__(256)
k_pre(const float* __restrict__ x,
      const float* __restrict__ w_ego_u,
      const float* __restrict__ w_layer_u,
      const float* __restrict__ n_imp, int N)
{
    int lane = threadIdx.x & 31;
    int gw = (blockIdx.x * blockDim.x + threadIdx.x) >> 5;
    int nw = gridDim.x * (blockDim.x >> 5);
    const float4* x4 = (const float4*)x;

    float4 wea = __ldg(((const float4*)w_ego_u)   + lane);
    float4 web = __ldg(((const float4*)w_ego_u)   + lane + 32);
    float4 wla = __ldg(((const float4*)w_layer_u) + lane);
    float4 wlb = __ldg(((const float4*)w_layer_u) + lane + 32);

    for (int n = gw * 2; n < N; n += nw * 2) {
        bool two = (n + 1 < N);
        float4 a0 = __ldg(x4 + (size_t)n * 64 + lane);
        float4 b0 = __ldg(x4 + (size_t)n * 64 + lane + 32);
        int n1 = two ? n + 1 : n;
        float4 a1 = __ldg(x4 + (size_t)n1 * 64 + lane);
        float4 b1 = __ldg(x4 + (size_t)n1 * 64 + lane + 32);

        float nu0 = sq8(a0, b0, wea, web);
        float su0 = dot4(a0, wla) + dot4(b0, wlb);
        float nu1 = sq8(a1, b1, wea, web);
        float su1 = dot4(a1, wla) + dot4(b1, wlb);

        nu0 += __shfl_xor_sync(0xffffffffu, nu0, 16);
        su0 += __shfl_xor_sync(0xffffffffu, su0, 16);
        nu1 += __shfl_xor_sync(0xffffffffu, nu1, 16);
        su1 += __shfl_xor_sync(0xffffffffu, su1, 16);
        bool hi16 = (lane & 16) != 0;
        float v0 = hi16 ? su0 : nu0;      // lanes<16: nu, >=16: su
        float v1 = hi16 ? su1 : nu1;
        #pragma unroll
        for (int o = 8; o; o >>= 1) {
            v0 += __shfl_xor_sync(0xffffffffu, v0, o);
            v1 += __shfl_xor_sync(0xffffffffu, v1, o);
        }
        float su0f = __shfl_sync(0xffffffffu, v0, 16);
        float su1f = __shfl_sync(0xffffffffu, v1, 16);
        if (lane == 0) {
            g_node[n] = make_float4(1.0f / fmaxf(sqrtf(v0), 1e-6f), su0f,
                                    0.5f * __ldg(n_imp + n), 0.0f);
            if (two)
                g_node[n1] = make_float4(1.0f / fmaxf(sqrtf(v1), 1e-6f), su1f,
                                         0.5f * __ldg(n_imp + n1), 0.0f);
        }
    }
}

// K3: edge scatter-add (4 edges per thread)
__global__ void k_edge(const int* __restrict__ edge_src,
                       const int* __restrict__ edge_dst, int E)
{
    int i = (blockIdx.x * blockDim.x + threadIdx.x) * 4;
    if (i + 3 < E) {
        int4 s = *(const int4*)(edge_src + i);
        int4 d = *(const int4*)(edge_dst + i);
        atomicAdd(&g_agg[d.x], g_sv[s.x]);
        atomicAdd(&g_agg[d.y], g_sv[s.y]);
        atomicAdd(&g_agg[d.z], g_sv[s.z]);
        atomicAdd(&g_agg[d.w], g_sv[s.w]);
    } else {
        for (int j = i; j < E; j++)
            atomicAdd(&g_agg[edge_dst[j]], g_sv[edge_src[j]]);
    }
}

// K4: dot-only candidate kernel, round-4 shape: 2 candidates per iteration,
// warp owns 16 CONTIGUOUS pairs so the g_groot row register-cache persists
// across iterations (batch_ptr sorted, run ~488 candidates).
__global__ void __launch_bounds__(256)
k_cand(const float* __restrict__ x,
       const int* __restrict__ u_ids,
       const int* __restrict__ batch_ptr, int M)
{
    int lane  = threadIdx.x & 31;
    int gwarp = (blockIdx.x * blockDim.x + threadIdx.x) >> 5;

    const float4* x4 = (const float4*)x;
    const float4* g4 = (const float4*)g_groot;

    // odd-M tail handled by warp 0
    if ((M & 1) && gwarp == 0) {
        int m = M - 1;
        int u = __ldg(u_ids + m);
        int b = __ldg(batch_ptr + m);
        float4 xa = __ldg(x4 + (size_t)u * 64 + lane);
        float4 xb = __ldg(x4 + (size_t)u * 64 + lane + 32);
        float4 ta = __ldg(g4 + (size_t)b * 64 + lane);
        float4 tb = __ldg(g4 + (size_t)b * 64 + lane + 32);
        float d = dot4(xa, ta) + dot4(xb, tb);
        #pragma unroll
        for (int o = 16; o; o >>= 1)
            d += __shfl_xor_sync(0xffffffffu, d, o);
        if (lane == 0) {
            float4 nd = __ldg((const float4*)g_node + u);
            float2 rs = __ldg(g_rootsc + b);
            float p = (d * rs.x * nd.x + tanhf(g_agg[m] + nd.y)) * nd.z * rs.y;
            g_pu[m] = p;
            atomicMax(&g_pnorm[b], f2key(p));
        }
    }

    int npairs = M >> 1;
    int p0 = gwarp * 16;
    if (p0 >= npairs) return;
    int p1 = p0 + 16; if (p1 > npairs) p1 = npairs;

    int bcache = -1;
    float4 ga = make_float4(0.f, 0.f, 0.f, 0.f), gb = ga;

    for (int p = p0; p < p1; p++) {
        int m0 = p * 2;
        int2 uu = *(const int2*)(u_ids + m0);
        int2 bb = *(const int2*)(batch_ptr + m0);

        float4 xa0 = __ldg(x4 + (size_t)uu.x * 64 + lane);
        float4 xb0 = __ldg(x4 + (size_t)uu.x * 64 + lane + 32);
        float4 xa1 = __ldg(x4 + (size_t)uu.y * 64 + lane);
        float4 xb1 = __ldg(x4 + (size_t)uu.y * 64 + lane + 32);

        if (bb.x != bcache) {                      // warp-uniform
            ga = __ldg(g4 + (size_t)bb.x * 64 + lane);
            gb = __ldg(g4 + (size_t)bb.x * 64 + lane + 32);
            bcache = bb.x;
        }
        float d0 = dot4(xa0, ga) + dot4(xb0, gb);
        float d1;
        if (bb.y == bb.x) {                        // warp-uniform, ~99.8%
            d1 = dot4(xa1, ga) + dot4(xb1, gb);
        } else {
            float4 ta = __ldg(g4 + (size_t)bb.y * 64 + lane);
            float4 tb = __ldg(g4 + (size_t)bb.y * 64 + lane + 32);
            d1 = dot4(xa1, ta) + dot4(xb1, tb);
        }

        // folded reduction: 2 dots in 6 shuffles
        d0 += __shfl_xor_sync(0xffffffffu, d0, 16);
        d1 += __shfl_xor_sync(0xffffffffu, d1, 16);
        float d = (lane & 16) ? d1 : d0;
        #pragma unroll
        for (int o = 8; o; o >>= 1)
            d += __shfl_xor_sync(0xffffffffu, d, o);
        // lanes 0 and 16 hold cand0 / cand1

        if ((lane & 15) == 0) {
            bool second = lane != 0;
            int m = second ? m0 + 1 : m0;
            int u = second ? uu.y : uu.x;
            int b = second ? bb.y : bb.x;
            float4 nd = __ldg((const float4*)g_node + u);  // {invnu, su, hni}
            float2 rs = __ldg(g_rootsc + b);               // {invnr, bf}
            float p = (d * rs.x * nd.x + tanhf(g_agg[m] + nd.y)) * nd.z * rs.y;
            g_pu[m] = p;
            atomicMax(&g_pnorm[b], f2key(p));
        }
    }
}

// K5: normalize + nan/inf replace + clip (vectorized)
__global__ void k_final(const int* __restrict__ batch_ptr,
                        float* __restrict__ out, int M)
{
    int m = (blockIdx.x * blockDim.x + threadIdx.x) * 4;
    if (m + 3 < M) {
        int4   bp = *(const int4*)(batch_ptr + m);
        float4 pu = *(const float4*)(g_pu + m);
        float4 r;
        {
            float p = pu.x / key2f(g_pnorm[bp.x]) + 1.0f;
            if (isnan(p)) p = 0.0f; else if (isinf(p)) p = 1.0f;
            r.x = fminf(fmaxf(p, 1e-5f), 1.0f);
        }
        {
            float p = pu.y / key2f(g_pnorm[bp.y]) + 1.0f;
            if (isnan(p)) p = 0.0f; else if (isinf(p)) p = 1.0f;
            r.y = fminf(fmaxf(p, 1e-5f), 1.0f);
        }
        {
            float p = pu.z / key2f(g_pnorm[bp.z]) + 1.0f;
            if (isnan(p)) p = 0.0f; else if (isinf(p)) p = 1.0f;
            r.z = fminf(fmaxf(p, 1e-5f), 1.0f);
        }
        {
            float p = pu.w / key2f(g_pnorm[bp.w]) + 1.0f;
            if (isnan(p)) p = 0.0f; else if (isinf(p)) p = 1.0f;
            r.w = fminf(fmaxf(p, 1e-5f), 1.0f);
        }
        *(float4*)(out + m) = r;
    } else {
        for (int j = m; j < M; j++) {
            float p = g_pu[j] / key2f(g_pnorm[batch_ptr[j]]) + 1.0f;
            if (isnan(p)) p = 0.0f; else if (isinf(p)) p = 1.0f;
            out[j] = fminf(fmaxf(p, 1e-5f), 1.0f);
        }
    }
}

extern "C" void kernel_launch(void* const* d_in, const int* in_sizes, int n_in,
                              void* d_out, int out_size)
{
    const float* x           = (const float*)d_in[0];
    const float* w_ego_root  = (const float*)d_in[1];
    const float* w_ego_u     = (const float*)d_in[2];
    const float* w_layer_v   = (const float*)d_in[3];
    const float* w_layer_u   = (const float*)d_in[4];
    const float* n_imp       = (const float*)d_in[5];
    const float* budgets     = (const float*)d_in[6];
    const int*   batch_nodes = (const int*)d_in[7];
    const int*   u_ids       = (const int*)d_in[8];
    const int*   batch_ptr   = (const int*)d_in[9];
    const int*   edge_src    = (const int*)d_in[10];
    const int*   edge_dst    = (const int*)d_in[11];
    float* out = (float*)d_out;

    int B = in_sizes[7];
    int M = in_sizes[8];
    int E = in_sizes[10];
    int N = in_sizes[0] / FDIM;

    k_root<<<B, FDIM>>>(x, w_ego_root, w_ego_u, w_layer_v, budgets,
                        batch_nodes, B, M);
    k_pre<<<2048, 256>>>(x, w_ego_u, w_layer_u, n_imp, N);
    k_edge<<<(E / 4 + 255) / 256, 256>>>(edge_src, edge_dst, E);

    int npairs = M >> 1;
    int nwarps = (npairs + 15) / 16;
    int nblocks = (nwarps + 7) / 8;
    if (nblocks < 1) nblocks = 1;
    k_cand<<<nblocks, 256>>>(x, u_ids, batch_ptr, M);

    k_final<<<(M / 4 + 255) / 256, 256>>>(batch_ptr, out, M);
}

// round 7
// speedup vs baseline: 1.4204x; 1.1713x over previous
#include <cuda_runtime.h>
#include <math.h>

#define FDIM 256
#define BMAX 1024
#define MMAX 500000
#define PAIRS 16

// Scratch (allocation-free: __device__ globals)
__device__ float    g_groot[BMAX * FDIM];   // per-root x_r * w_ego_root * w_ego_u
__device__ float2   g_rootsc[BMAX];         // {1/max(nr,eps), budgets/200}
__device__ float    g_sv[BMAX];             // x_r . w_layer_v
__device__ unsigned g_pnorm[BMAX];          // encoded float max
__device__ float    g_agg[MMAX];            // segment_sum(sv[edge_src] -> edge_dst)
__device__ float    g_pu[MMAX];             // p_u before normalization

__device__ __forceinline__ unsigned f2key(float f) {
    unsigned u = __float_as_uint(f);
    return (u & 0x80000000u) ? ~u : (u | 0x80000000u);
}
__device__ __forceinline__ float key2f(unsigned k) {
    unsigned u = (k & 0x80000000u) ? (k ^ 0x80000000u) : ~k;
    return __uint_as_float(u);
}
__device__ __forceinline__ float dot4(float4 a, float4 b) {
    return a.x * b.x + a.y * b.y + a.z * b.z + a.w * b.w;
}
__device__ __forceinline__ float sq8(float4 a, float4 b, float4 wa, float4 wb) {
    float x0 = a.x*wa.x, x1 = a.y*wa.y, x2 = a.z*wa.z, x3 = a.w*wa.w;
    float y0 = b.x*wb.x, y1 = b.y*wb.y, y2 = b.z*wb.z, y3 = b.w*wb.w;
    return x0*x0 + x1*x1 + x2*x2 + x3*x3 + y0*y0 + y1*y1 + y2*y2 + y3*y3;
}

// K1: per-root precompute (one block per root) + zero g_agg (strided).
__global__ void k_root(const float* __restrict__ x,
                       const float* __restrict__ w_ego_root,
                       const float* __restrict__ w_ego_u,
                       const float* __restrict__ w_layer_v,
                       const float* __restrict__ budgets,
                       const int*   __restrict__ batch_nodes,
                       int B, int M)
{
    int b = blockIdx.x;
    int f = threadIdx.x;

    for (int j = b * FDIM + f; j < M; j += gridDim.x * FDIM) g_agg[j] = 0.0f;

    float xr = x[(size_t)batch_nodes[b] * FDIM + f];
    float h  = xr * w_ego_root[f];
    g_groot[b * FDIM + f] = h * w_ego_u[f];
    float s1 = h * h;
    float s2 = xr * w_layer_v[f];

    __shared__ float sh1[8], sh2[8];
    #pragma unroll
    for (int o = 16; o; o >>= 1) {
        s1 += __shfl_xor_sync(0xffffffffu, s1, o);
        s2 += __shfl_xor_sync(0xffffffffu, s2, o);
    }
    int w = f >> 5, l = f & 31;
    if (l == 0) { sh1[w] = s1; sh2[w] = s2; }
    __syncthreads();
    if (f == 0) {
        float t1 = 0.f, t2 = 0.f;
        #pragma unroll
        for (int i = 0; i < 8; i++) { t1 += sh1[i]; t2 += sh2[i]; }
        g_rootsc[b] = make_float2(1.0f / fmaxf(sqrtf(t1), 1e-6f),
                                  budgets[b] * (1.0f / 200.0f));
        g_sv[b] = t2;
        g_pnorm[b] = f2key(-INFINITY);
    }
}

// K3: edge scatter-add (4 edges per thread)
__global__ void k_edge(const int* __restrict__ edge_src,
                       const int* __restrict__ edge_dst, int E)
{
    int i = (blockIdx.x * blockDim.x + threadIdx.x) * 4;
    if (i + 3 < E) {
        int4 s = *(const int4*)(edge_src + i);
        int4 d = *(const int4*)(edge_dst + i);
        atomicAdd(&g_agg[d.x], g_sv[s.x]);
        atomicAdd(&g_agg[d.y], g_sv[s.y]);
        atomicAdd(&g_agg[d.z], g_sv[s.z]);
        atomicAdd(&g_agg[d.w], g_sv[s.w]);
    } else {
        for (int j = i; j < E; j++)
            atomicAdd(&g_agg[edge_dst[j]], g_sv[edge_src[j]]);
    }
}

// K4: fused candidate kernel, 2 candidates per iteration, software-pipelined:
// next pair's x rows prefetched during current compute; finalize scalars
// loaded unguarded at iteration top so the post-reduction tail is pure ALU.
__global__ void __launch_bounds__(256)
k_cand(const float* __restrict__ x,
       const float* __restrict__ w_ego_u,
       const float* __restrict__ w_layer_u,
       const float* __restrict__ n_imp,
       const int* __restrict__ u_ids,
       const int* __restrict__ batch_ptr, int M)
{
    int lane  = threadIdx.x & 31;
    int gwarp = (blockIdx.x * blockDim.x + threadIdx.x) >> 5;

    const float4* x4  = (const float4*)x;
    const float4* g4  = (const float4*)g_groot;
    const float4* w4e = (const float4*)w_ego_u;
    const float4* w4l = (const float4*)w_layer_u;

    // odd-M tail handled solo by warp 0
    if ((M & 1) && gwarp == 0) {
        int m = M - 1;
        int u = __ldg(u_ids + m);
        int b = __ldg(batch_ptr + m);
        float4 xa = __ldg(x4 + (size_t)u * 64 + lane);
        float4 xb = __ldg(x4 + (size_t)u * 64 + lane + 32);
        float4 ta = __ldg(g4 + (size_t)b * 64 + lane);
        float4 tb = __ldg(g4 + (size_t)b * 64 + lane + 32);
        float4 ea = __ldg(w4e + lane), eb = __ldg(w4e + lane + 32);
        float4 la = __ldg(w4l + lane), lb = __ldg(w4l + lane + 32);
        float d = dot4(xa, ta) + dot4(xb, tb);
        float n = sq8(xa, xb, ea, eb);
        float s = dot4(xa, la) + dot4(xb, lb);
        #pragma unroll
        for (int o = 16; o; o >>= 1) {
            d += __shfl_xor_sync(0xffffffffu, d, o);
            n += __shfl_xor_sync(0xffffffffu, n, o);
            s += __shfl_xor_sync(0xffffffffu, s, o);
        }
        if (lane == 0) {
            float2 rs = __ldg(g_rootsc + b);
            float invnu = 1.0f / fmaxf(sqrtf(n), 1e-6f);
            float p = (d * rs.x * invnu + tanhf(g_agg[m] + s))
                      * (0.5f * __ldg(n_imp + u)) * rs.y;
            g_pu[m] = p;
            atomicMax(&g_pnorm[b], f2key(p));
        }
    }

    int npairs = M >> 1;
    int p0 = gwarp * PAIRS;
    if (p0 >= npairs) return;
    int p1 = p0 + PAIRS; if (p1 > npairs) p1 = npairs;

    // prologue: current pair's indices + x rows
    int2 uu = *(const int2*)(u_ids + 2 * p0);
    int2 bb = *(const int2*)(batch_ptr + 2 * p0);
    float4 xa0 = __ldg(x4 + (size_t)uu.x * 64 + lane);
    float4 xb0 = __ldg(x4 + (size_t)uu.x * 64 + lane + 32);
    float4 xa1 = __ldg(x4 + (size_t)uu.y * 64 + lane);
    float4 xb1 = __ldg(x4 + (size_t)uu.y * 64 + lane + 32);

    int bcache = -1;
    float4 ga = make_float4(0.f, 0.f, 0.f, 0.f), gb = ga;

    for (int p = p0; p < p1; p++) {
        // ---- prefetch next pair (always 4 wide loads in flight) ----
        int pn = (p + 1 < p1) ? p + 1 : p;
        int2 uun = *(const int2*)(u_ids + 2 * pn);
        int2 bbn = *(const int2*)(batch_ptr + 2 * pn);
        float4 nxa0 = __ldg(x4 + (size_t)uun.x * 64 + lane);
        float4 nxb0 = __ldg(x4 + (size_t)uun.x * 64 + lane + 32);
        float4 nxa1 = __ldg(x4 + (size_t)uun.y * 64 + lane);
        float4 nxb1 = __ldg(x4 + (size_t)uun.y * 64 + lane + 32);

        // ---- finalize scalars: uniform, unguarded, issued early ----
        int m0 = 2 * p;
        float  ni0 = __ldg(n_imp + uu.x);
        float  ni1 = __ldg(n_imp + uu.y);
        float2 rs0 = __ldg(g_rootsc + bb.x);
        float2 rs1 = __ldg(g_rootsc + bb.y);
        float2 ag  = *(const float2*)(g_agg + m0);

        // ---- weights (L1-hot, reload each iteration to save registers) ----
        float4 wea = __ldg(w4e + lane);
        float4 web = __ldg(w4e + lane + 32);
        float4 wla = __ldg(w4l + lane);
        float4 wlb = __ldg(w4l + lane + 32);

        // ---- g row, cached across iterations (sorted batch_ptr) ----
        if (bb.x != bcache) {
            ga = __ldg(g4 + (size_t)bb.x * 64 + lane);
            gb = __ldg(g4 + (size_t)bb.x * 64 + lane + 32);
            bcache = bb.x;
        }
        float d0 = dot4(xa0, ga) + dot4(xb0, gb);
        float d1;
        if (bb.y == bb.x) {
            d1 = dot4(xa1, ga) + dot4(xb1, gb);
        } else {
            float4 ta = __ldg(g4 + (size_t)bb.y * 64 + lane);
            float4 tb = __ldg(g4 + (size_t)bb.y * 64 + lane + 32);
            d1 = dot4(xa1, ta) + dot4(xb1, tb);
        }

        float nu0 = sq8(xa0, xb0, wea, web);
        float nu1 = sq8(xa1, xb1, wea, web);
        float su0 = dot4(xa0, wla) + dot4(xb0, wlb);
        float su1 = dot4(xa1, wla) + dot4(xb1, wlb);

        // ---- folded reduction: 6 sums in 18 shuffles ----
        dot4(xa0, ga);  // no-op value reuse hint removed by compiler
        d0  += __shfl_xor_sync(0xffffffffu, d0,  16);
        d1  += __shfl_xor_sync(0xffffffffu, d1,  16);
        nu0 += __shfl_xor_sync(0xffffffffu, nu0, 16);
        nu1 += __shfl_xor_sync(0xffffffffu, nu1, 16);
        su0 += __shfl_xor_sync(0xffffffffu, su0, 16);
        su1 += __shfl_xor_sync(0xffffffffu, su1, 16);
        bool hi = (lane & 16) != 0;
        float d = hi ? d1 : d0;
        float n = hi ? nu1 : nu0;
        float s = hi ? su1 : su0;
        #pragma unroll
        for (int o = 8; o; o >>= 1) {
            d += __shfl_xor_sync(0xffffffffu, d, o);
            n += __shfl_xor_sync(0xffffffffu, n, o);
            s += __shfl_xor_sync(0xffffffffu, s, o);
        }
        // lanes 0 / 16 hold cand0 / cand1

        if ((lane & 15) == 0) {
            bool second = lane != 0;
            float  ni  = second ? ni1 : ni0;
            float2 rs  = second ? rs1 : rs0;
            float  agm = second ? ag.y : ag.x;
            float invnu = 1.0f / fmaxf(sqrtf(n), 1e-6f);
            float pv = (d * rs.x * invnu + tanhf(agm + s)) * (0.5f * ni) * rs.y;
            g_pu[m0 + (second ? 1 : 0)] = pv;
            atomicMax(&g_pnorm[second ? bb.y : bb.x], f2key(pv));
        }

        // rotate pipeline
        uu = uun; bb = bbn;
        xa0 = nxa0; xb0 = nxb0; xa1 = nxa1; xb1 = nxb1;
    }
}

// K5: normalize + nan/inf replace + clip (vectorized)
__global__ void k_final(const int* __restrict__ batch_ptr,
                        float* __restrict__ out, int M)
{
    int m = (blockIdx.x * blockDim.x + threadIdx.x) * 4;
    if (m + 3 < M) {
        int4   bp = *(const int4*)(batch_ptr + m);
        float4 pu = *(const float4*)(g_pu + m);
        float4 r;
        {
            float p = pu.x / key2f(g_pnorm[bp.x]) + 1.0f;
            if (isnan(p)) p = 0.0f; else if (isinf(p)) p = 1.0f;
            r.x = fminf(fmaxf(p, 1e-5f), 1.0f);
        }
        {
            float p = pu.y / key2f(g_pnorm[bp.y]) + 1.0f;
            if (isnan(p)) p = 0.0f; else if (isinf(p)) p = 1.0f;
            r.y = fminf(fmaxf(p, 1e-5f), 1.0f);
        }
        {
            float p = pu.z / key2f(g_pnorm[bp.z]) + 1.0f;
            if (isnan(p)) p = 0.0f; else if (isinf(p)) p = 1.0f;
            r.z = fminf(fmaxf(p, 1e-5f), 1.0f);
        }
        {
            float p = pu.w / key2f(g_pnorm[bp.w]) + 1.0f;
            if (isnan(p)) p = 0.0f; else if (isinf(p)) p = 1.0f;
            r.w = fminf(fmaxf(p, 1e-5f), 1.0f);
        }
        *(float4*)(out + m) = r;
    } else {
        for (int j = m; j < M; j++) {
            float p = g_pu[j] / key2f(g_pnorm[batch_ptr[j]]) + 1.0f;
            if (isnan(p)) p = 0.0f; else if (isinf(p)) p = 1.0f;
            out[j] = fminf(fmaxf(p, 1e-5f), 1.0f);
        }
    }
}

extern "C" void kernel_launch(void* const* d_in, const int* in_sizes, int n_in,
                              void* d_out, int out_size)
{
    const float* x           = (const float*)d_in[0];
    const float* w_ego_root  = (const float*)d_in[1];
    const float* w_ego_u     = (const float*)d_in[2];
    const float* w_layer_v   = (const float*)d_in[3];
    const float* w_layer_u   = (const float*)d_in[4];
    const float* n_imp       = (const float*)d_in[5];
    const float* budgets     = (const float*)d_in[6];
    const int*   batch_nodes = (const int*)d_in[7];
    const int*   u_ids       = (const int*)d_in[8];
    const int*   batch_ptr   = (const int*)d_in[9];
    const int*   edge_src    = (const int*)d_in[10];
    const int*   edge_dst    = (const int*)d_in[11];
    float* out = (float*)d_out;

    int B = in_sizes[7];
    int M = in_sizes[8];
    int E = in_sizes[10];

    k_root<<<B, FDIM>>>(x, w_ego_root, w_ego_u, w_layer_v, budgets,
                        batch_nodes, B, M);
    k_edge<<<(E / 4 + 255) / 256, 256>>>(edge_src, edge_dst, E);

    int npairs = M >> 1;
    int nwarps = (npairs + PAIRS - 1) / PAIRS;
    int nblocks = (nwarps + 7) / 8;
    if (nblocks < 1) nblocks = 1;
    k_cand<<<nblocks, 256>>>(x, w_ego_u, w_layer_u, n_imp, u_ids, batch_ptr, M);

    k_final<<<(M / 4 + 255) / 256, 256>>>(batch_ptr, out, M);
}

// round 9
// speedup vs baseline: 1.7145x; 1.2070x over previous
#include <cuda_runtime.h>
#include <math.h>

#define FDIM 256
#define BMAX 1024
#define MMAX 500000
#define CPW  32      // candidates per warp (8 iterations x 4)

// Scratch (allocation-free: __device__ globals)
__device__ float    g_groot[BMAX * FDIM];   // per-root x_r * w_ego_root * w_ego_u
__device__ float2   g_rootsc[BMAX];         // {1/max(nr,eps), budgets/200}
__device__ float    g_sv[BMAX];             // x_r . w_layer_v
__device__ unsigned g_pnorm[BMAX];          // encoded float max
__device__ float    g_agg[MMAX];            // segment_sum(sv[edge_src] -> edge_dst)
__device__ float    g_pu[MMAX];             // p_u before normalization

__device__ __forceinline__ unsigned f2key(float f) {
    unsigned u = __float_as_uint(f);
    return (u & 0x80000000u) ? ~u : (u | 0x80000000u);
}
__device__ __forceinline__ float key2f(unsigned k) {
    unsigned u = (k & 0x80000000u) ? (k ^ 0x80000000u) : ~k;
    return __uint_as_float(u);
}
__device__ __forceinline__ float dot4(float4 a, float4 b) {
    return a.x * b.x + a.y * b.y + a.z * b.z + a.w * b.w;
}
__device__ __forceinline__ float sq4(float4 a, float4 w) {
    float t0 = a.x * w.x, t1 = a.y * w.y, t2 = a.z * w.z, t3 = a.w * w.w;
    return t0 * t0 + t1 * t1 + t2 * t2 + t3 * t3;
}

// K1: per-root precompute (one block per root) + zero g_agg (strided).
__global__ void k_root(const float* __restrict__ x,
                       const float* __restrict__ w_ego_root,
                       const float* __restrict__ w_ego_u,
                       const float* __restrict__ w_layer_v,
                       const float* __restrict__ budgets,
                       const int*   __restrict__ batch_nodes,
                       int B, int M)
{
    int b = blockIdx.x;
    int f = threadIdx.x;

    for (int j = b * FDIM + f; j < M; j += gridDim.x * FDIM) g_agg[j] = 0.0f;

    float xr = x[(size_t)batch_nodes[b] * FDIM + f];
    float h  = xr * w_ego_root[f];
    g_groot[b * FDIM + f] = h * w_ego_u[f];
    float s1 = h * h;
    float s2 = xr * w_layer_v[f];

    __shared__ float sh1[8], sh2[8];
    #pragma unroll
    for (int o = 16; o; o >>= 1) {
        s1 += __shfl_xor_sync(0xffffffffu, s1, o);
        s2 += __shfl_xor_sync(0xffffffffu, s2, o);
    }
    int w = f >> 5, l = f & 31;
    if (l == 0) { sh1[w] = s1; sh2[w] = s2; }
    __syncthreads();
    if (f == 0) {
        float t1 = 0.f, t2 = 0.f;
        #pragma unroll
        for (int i = 0; i < 8; i++) { t1 += sh1[i]; t2 += sh2[i]; }
        g_rootsc[b] = make_float2(1.0f / fmaxf(sqrtf(t1), 1e-6f),
                                  budgets[b] * (1.0f / 200.0f));
        g_sv[b] = t2;
        g_pnorm[b] = f2key(-INFINITY);
    }
}

// K3: edge scatter-add (4 edges per thread)
__global__ void k_edge(const int* __restrict__ edge_src,
                       const int* __restrict__ edge_dst, int E)
{
    int i = (blockIdx.x * blockDim.x + threadIdx.x) * 4;
    if (i + 3 < E) {
        int4 s = *(const int4*)(edge_src + i);
        int4 d = *(const int4*)(edge_dst + i);
        atomicAdd(&g_agg[d.x], g_sv[s.x]);
        atomicAdd(&g_agg[d.y], g_sv[s.y]);
        atomicAdd(&g_agg[d.z], g_sv[s.z]);
        atomicAdd(&g_agg[d.w], g_sv[s.w]);
    } else {
        for (int j = i; j < E; j++)
            atomicAdd(&g_agg[edge_dst[j]], g_sv[edge_src[j]]);
    }
}

// K4: 8-lanes-per-candidate layout. Warp = 4 candidates in parallel.
// Each lane issues 8 independent x float4 loads (4KB in flight per warp),
// reduction is 3 shuffle rounds, finalize is unguarded on all lanes.
__global__ void __launch_bounds__(256)
k_cand(const float* __restrict__ x,
       const float* __restrict__ w_ego_u,
       const float* __restrict__ w_layer_u,
       const float* __restrict__ n_imp,
       const int* __restrict__ u_ids,
       const int* __restrict__ batch_ptr, int M)
{
    __shared__ __align__(16) float4 s_we[64];
    __shared__ __align__(16) float4 s_wl[64];
    {
        int t = threadIdx.x;
        if (t < 64)        s_we[t]      = ((const float4*)w_ego_u)[t];
        else if (t < 128)  s_wl[t - 64] = ((const float4*)w_layer_u)[t - 64];
    }
    __syncthreads();

    int lane  = threadIdx.x & 31;
    int gwarp = (blockIdx.x * blockDim.x + threadIdx.x) >> 5;
    int c = lane >> 3;          // candidate slot 0..3
    int s = lane & 7;           // sublane 0..7

    const float4* x4 = (const float4*)x;
    const float4* g4 = (const float4*)g_groot;

    int Mmain = M & ~3;

    // tail: warp 0 of the grid handles [Mmain, M) with the 32-lane path
    if (gwarp == 0 && Mmain < M) {
        for (int m = Mmain; m < M; m++) {
            int u = __ldg(u_ids + m);
            int b = __ldg(batch_ptr + m);
            float4 xa = __ldg(x4 + (size_t)u * 64 + lane);
            float4 xb = __ldg(x4 + (size_t)u * 64 + lane + 32);
            float4 ta = __ldg(g4 + (size_t)b * 64 + lane);
            float4 tb = __ldg(g4 + (size_t)b * 64 + lane + 32);
            float4 ea = s_we[lane], eb = s_we[lane + 32];
            float4 la = s_wl[lane], lb = s_wl[lane + 32];
            float d = dot4(xa, ta) + dot4(xb, tb);
            float n = sq4(xa, ea) + sq4(xb, eb);
            float sv = dot4(xa, la) + dot4(xb, lb);
            #pragma unroll
            for (int o = 16; o; o >>= 1) {
                d  += __shfl_xor_sync(0xffffffffu, d,  o);
                n  += __shfl_xor_sync(0xffffffffu, n,  o);
                sv += __shfl_xor_sync(0xffffffffu, sv, o);
            }
            if (lane == 0) {
                float2 rs = __ldg(g_rootsc + b);
                float invnu = 1.0f / fmaxf(sqrtf(n), 1e-6f);
                float p = (d * rs.x * invnu + tanhf(g_agg[m] + sv))
                          * (0.5f * __ldg(n_imp + u)) * rs.y;
                g_pu[m] = p;
                atomicMax(&g_pnorm[b], f2key(p));
            }
        }
    }

    int base = gwarp * CPW;
    if (base >= Mmain) return;
    int lim = base + CPW; if (lim > Mmain) lim = Mmain;

    for (int m0 = base; m0 < lim; m0 += 4) {
        int4 uu = *(const int4*)(u_ids + m0);
        int4 bb = *(const int4*)(batch_ptr + m0);
        int u = (c == 0) ? uu.x : (c == 1) ? uu.y : (c == 2) ? uu.z : uu.w;
        int b = (c == 0) ? bb.x : (c == 1) ? bb.y : (c == 2) ? bb.z : bb.w;

        // 8 independent wide loads per lane — 4KB in flight per warp
        const float4* xr = x4 + (size_t)u * 64 + s;
        float4 xv0 = __ldg(xr);
        float4 xv1 = __ldg(xr + 8);
        float4 xv2 = __ldg(xr + 16);
        float4 xv3 = __ldg(xr + 24);
        float4 xv4 = __ldg(xr + 32);
        float4 xv5 = __ldg(xr + 40);
        float4 xv6 = __ldg(xr + 48);
        float4 xv7 = __ldg(xr + 56);

        // finalize scalars, hoisted & unguarded (group-uniform addresses)
        float  ni = __ldg(n_imp + u);
        float2 rs = __ldg(g_rootsc + b);
        float  ag = __ldg(g_agg + m0 + c);

        const float4* gr = g4 + (size_t)b * 64 + s;
        float dot = 0.f, nu = 0.f, su = 0.f;
        {
            float4 gv, ev, lv;
            gv = __ldg(gr);      ev = s_we[s];      lv = s_wl[s];
            dot += dot4(xv0, gv); nu += sq4(xv0, ev); su += dot4(xv0, lv);
            gv = __ldg(gr + 8);  ev = s_we[s + 8];  lv = s_wl[s + 8];
            dot += dot4(xv1, gv); nu += sq4(xv1, ev); su += dot4(xv1, lv);
            gv = __ldg(gr + 16); ev = s_we[s + 16]; lv = s_wl[s + 16];
            dot += dot4(xv2, gv); nu += sq4(xv2, ev); su += dot4(xv2, lv);
            gv = __ldg(gr + 24); ev = s_we[s + 24]; lv = s_wl[s + 24];
            dot += dot4(xv3, gv); nu += sq4(xv3, ev); su += dot4(xv3, lv);
            gv = __ldg(gr + 32); ev = s_we[s + 32]; lv = s_wl[s + 32];
            dot += dot4(xv4, gv); nu += sq4(xv4, ev); su += dot4(xv4, lv);
            gv = __ldg(gr + 40); ev = s_we[s + 40]; lv = s_wl[s + 40];
            dot += dot4(xv5, gv); nu += sq4(xv5, ev); su += dot4(xv5, lv);
            gv = __ldg(gr + 48); ev = s_we[s + 48]; lv = s_wl[s + 48];
            dot += dot4(xv6, gv); nu += sq4(xv6, ev); su += dot4(xv6, lv);
            gv = __ldg(gr + 56); ev = s_we[s + 56]; lv = s_wl[s + 56];
            dot += dot4(xv7, gv); nu += sq4(xv7, ev); su += dot4(xv7, lv);
        }

        // 3-round reduction within each 8-lane group
        #pragma unroll
        for (int o = 4; o; o >>= 1) {
            dot += __shfl_xor_sync(0xffffffffu, dot, o);
            nu  += __shfl_xor_sync(0xffffffffu, nu,  o);
            su  += __shfl_xor_sync(0xffffffffu, su,  o);
        }

        // finalize on ALL lanes (group-uniform values)
        float invnu = 1.0f / fmaxf(sqrtf(nu), 1e-6f);
        float p = (dot * rs.x * invnu + tanhf(ag + su)) * (0.5f * ni) * rs.y;
        unsigned key = f2key(p);

        if (s == 0) g_pu[m0 + c] = p;   // 4 lanes, contiguous 16B -> 1 txn

        if (bb.x == bb.w) {             // sorted => all four equal
            unsigned k1 = key, t;
            t = __shfl_xor_sync(0xffffffffu, k1, 8);  k1 = k1 > t ? k1 : t;
            t = __shfl_xor_sync(0xffffffffu, k1, 16); k1 = k1 > t ? k1 : t;
            if (lane == 0) atomicMax(&g_pnorm[bb.x], k1);
        } else {
            if (s == 0) atomicMax(&g_pnorm[b], key);
        }
    }
}

// K5: normalize + nan/inf replace + clip (vectorized)
__global__ void k_final(const int* __restrict__ batch_ptr,
                        float* __restrict__ out, int M)
{
    int m = (blockIdx.x * blockDim.x + threadIdx.x) * 4;
    if (m + 3 < M) {
        int4   bp = *(const int4*)(batch_ptr + m);
        float4 pu = *(const float4*)(g_pu + m);
        float4 r;
        {
            float p = pu.x / key2f(g_pnorm[bp.x]) + 1.0f;
            if (isnan(p)) p = 0.0f; else if (isinf(p)) p = 1.0f;
            r.x = fminf(fmaxf(p, 1e-5f), 1.0f);
        }
        {
            float p = pu.y / key2f(g_pnorm[bp.y]) + 1.0f;
            if (isnan(p)) p = 0.0f; else if (isinf(p)) p = 1.0f;
            r.y = fminf(fmaxf(p, 1e-5f), 1.0f);
        }
        {
            float p = pu.z / key2f(g_pnorm[bp.z]) + 1.0f;
            if (isnan(p)) p = 0.0f; else if (isinf(p)) p = 1.0f;
            r.z = fminf(fmaxf(p, 1e-5f), 1.0f);
        }
        {
            float p = pu.w / key2f(g_pnorm[bp.w]) + 1.0f;
            if (isnan(p)) p = 0.0f; else if (isinf(p)) p = 1.0f;
            r.w = fminf(fmaxf(p, 1e-5f), 1.0f);
        }
        *(float4*)(out + m) = r;
    } else {
        for (int j = m; j < M; j++) {
            float p = g_pu[j] / key2f(g_pnorm[batch_ptr[j]]) + 1.0f;
            if (isnan(p)) p = 0.0f; else if (isinf(p)) p = 1.0f;
            out[j] = fminf(fmaxf(p, 1e-5f), 1.0f);
        }
    }
}

extern "C" void kernel_launch(void* const* d_in, const int* in_sizes, int n_in,
                              void* d_out, int out_size)
{
    const float* x           = (const float*)d_in[0];
    const float* w_ego_root  = (const float*)d_in[1];
    const float* w_ego_u     = (const float*)d_in[2];
    const float* w_layer_v   = (const float*)d_in[3];
    const float* w_layer_u   = (const float*)d_in[4];
    const float* n_imp       = (const float*)d_in[5];
    const float* budgets     = (const float*)d_in[6];
    const int*   batch_nodes = (const int*)d_in[7];
    const int*   u_ids       = (const int*)d_in[8];
    const int*   batch_ptr   = (const int*)d_in[9];
    const int*   edge_src    = (const int*)d_in[10];
    const int*   edge_dst    = (const int*)d_in[11];
    float* out = (float*)d_out;

    int B = in_sizes[7];
    int M = in_sizes[8];
    int E = in_sizes[10];

    k_root<<<B, FDIM>>>(x, w_ego_root, w_ego_u, w_layer_v, budgets,
                        batch_nodes, B, M);
    k_edge<<<(E / 4 + 255) / 256, 256>>>(edge_src, edge_dst, E);

    int Mmain = M & ~3;
    int nwarps = (Mmain + CPW - 1) / CPW;
    int nblocks = (nwarps + 7) / 8;
    if (nblocks < 1) nblocks = 1;
    k_cand<<<nblocks, 256>>>(x, w_ego_u, w_layer_u, n_imp, u_ids, batch_ptr, M);

    k_final<<<(M / 4 + 255) / 256, 256>>>(batch_ptr, out, M);
}